// round 3
// baseline (speedup 1.0000x reference)
#include <cuda_runtime.h>

typedef unsigned long long ull;

// ---------------- problem constants ----------------
#define INS   224
#define NH    220
#define NB    48400
#define ICH   16
#define OCH   64
#define KTOT  400
#define NBANDS 220          // 1 row per band
#define PIX_PER_BAND 220
#define CHUNK 44            // 5 chunks per band

#define OUT_OFF_W   (OCH*NB)
#define OUT_OFF_EXP (OUT_OFF_W + OCH*KTOT)

// ---------------- scratch ----------------
__device__ float g_Wt[KTOT * OCH];                 // [ic][25][oc]
__device__ float g_y[NB * OCH];                    // (pixel, oc)
__device__ float g_Cpart[NBANDS * OCH * KTOT];     // 22.5 MB
__device__ float g_ytypart[NBANDS * OCH * OCH];
__device__ float g_colpart[NBANDS * OCH];
__device__ float g_Cred[20 * OCH * KTOT];
__device__ float g_ytyred[20 * OCH * OCH];
__device__ float g_Cfin[OCH * KTOT];
__device__ float g_ytyF[OCH * OCH];
__device__ float g_gfp[OCH];

// ---------------- f32x2 helpers ----------------
__device__ __forceinline__ ull pack2(float lo, float hi) {
    ull r; asm("mov.b64 %0, {%1,%2};" : "=l"(r) : "f"(lo), "f"(hi)); return r;
}
__device__ __forceinline__ float2 unpack2(ull v) {
    float2 f; asm("mov.b64 {%0,%1}, %2;" : "=f"(f.x), "=f"(f.y) : "l"(v)); return f;
}
#define FMA2(acc, a, b) asm("fma.rn.f32x2 %0, %1, %2, %0;" : "+l"(acc) : "l"(a), "l"(b))

// ======================================================================
// K0: transpose W -> g_Wt[ic*1600 + kk*64 + oc]
// ======================================================================
__global__ void k_prep(const float* __restrict__ W)
{
    int idx = blockIdx.x * 256 + threadIdx.x;
    if (idx >= KTOT * OCH) return;
    int oc = idx & 63;
    int t  = idx >> 6;
    int ic = t / 25, kk = t - ic * 25;
    g_Wt[idx] = W[oc * KTOT + ic * 25 + kk];
}

// ======================================================================
// K1: conv + inhibition. 128 thr, 8x8 px tile, thread = 2px x 16oc.
// grid (28, 28) = 784 blocks.
// ======================================================================
__global__ void __launch_bounds__(128)
k_conv(const float* __restrict__ x, float* __restrict__ dout)
{
    __shared__ float xs[12 * 13];
    __shared__ float ws[25 * 64];
    __shared__ float mtmp[4][64];

    const int tid = threadIdx.x;
    const int ocg = tid & 3;
    const int pg  = tid >> 2;          // 0..31
    const int li  = pg >> 2;           // 0..7
    const int lj0 = (pg & 3) * 2;      // 0,2,4,6
    const int i0  = blockIdx.y * 8;
    const int j0  = blockIdx.x * 8;
    const int oc0 = ocg * 16;

    ull acc2[2][8];
#pragma unroll
    for (int q = 0; q < 2; q++)
#pragma unroll
        for (int w = 0; w < 8; w++) acc2[q][w] = 0ULL;

    const int xbase = li * 13 + lj0;

    for (int ic = 0; ic < ICH; ic++) {
        __syncthreads();
        for (int lin = tid; lin < 12 * 13; lin += 128) {
            int r = lin / 13, c = lin - r * 13;
            int gi = min(i0 + r, INS - 1);
            int gj = min(j0 + c, INS - 1);
            xs[lin] = x[ic * (INS * INS) + gi * INS + gj];
        }
        const float4* wsrc = (const float4*)(g_Wt + ic * 1600);
        for (int v = tid; v < 400; v += 128)
            ((float4*)ws)[v] = wsrc[v];
        __syncthreads();

#pragma unroll 1
        for (int ki = 0; ki < 5; ki++) {
#pragma unroll
            for (int kj = 0; kj < 5; kj++) {
                ull xv2[2];
#pragma unroll
                for (int q = 0; q < 2; q++) {
                    float v = xs[xbase + ki * 13 + kj + q];
                    xv2[q] = pack2(v, v);
                }
                const ulonglong2* wp =
                    (const ulonglong2*)&ws[(ki * 5 + kj) * 64 + oc0];
#pragma unroll
                for (int w = 0; w < 4; w++) {
                    ulonglong2 ww = wp[w];
#pragma unroll
                    for (int q = 0; q < 2; q++) {
                        FMA2(acc2[q][2 * w],     xv2[q], ww.x);
                        FMA2(acc2[q][2 * w + 1], xv2[q], ww.y);
                    }
                }
            }
        }
    }

#pragma unroll
    for (int q = 0; q < 2; q++) {
        float m = 0.f;
#pragma unroll
        for (int w = 0; w < 8; w++) {
            float2 f = unpack2(acc2[q][w]);
            m = fmaxf(m, fmaxf(f.x, f.y));
        }
        mtmp[ocg][pg * 2 + q] = m;
    }
    __syncthreads();

    const int i = i0 + li;
    const int j = j0 + lj0;
    float minv[2];
#pragma unroll
    for (int q = 0; q < 2; q++) {
        float m = fmaxf(fmaxf(mtmp[0][pg * 2 + q], mtmp[1][pg * 2 + q]),
                        fmaxf(mtmp[2][pg * 2 + q], mtmp[3][pg * 2 + q]));
        minv[q] = 1.f / (m + 1e-9f);
    }

    if (i < NH && j < NH) {           // j even => j+1 also valid
        const int p = i * NH + j;
#pragma unroll
        for (int w = 0; w < 8; w += 2) {
            float vals[2][4];
#pragma unroll
            for (int q = 0; q < 2; q++) {
                float2 fa = unpack2(acc2[q][w]);
                float2 fb = unpack2(acc2[q][w + 1]);
                vals[q][0] = fa.x; vals[q][1] = fa.y;
                vals[q][2] = fb.x; vals[q][3] = fb.y;
            }
#pragma unroll
            for (int q = 0; q < 2; q++)
#pragma unroll
                for (int o = 0; o < 4; o++) {
                    float v = fmaxf(vals[q][o], 0.f) * minv[q];
                    float v2 = v * v;
                    vals[q][o] = v2 * v2 * v;
                }
            int obase = oc0 + 2 * w;
#pragma unroll
            for (int o = 0; o < 4; o++)
                *(float2*)&dout[(obase + o) * NB + p] =
                    make_float2(vals[0][o], vals[1][o]);
#pragma unroll
            for (int q = 0; q < 2; q++)
                *(float4*)&g_y[(p + q) * OCH + obase] =
                    make_float4(vals[q][0], vals[q][1], vals[q][2], vals[q][3]);
        }
    }
}

// ======================================================================
// K2: fused y^T@xf (kt 0..4) and y^T@y + colsums (kt==5).
// grid (6, 220), 128 threads. Band = one image row (220 px).
// ======================================================================
__global__ void __launch_bounds__(128)
k_hebb(const float* __restrict__ x)
{
    __shared__ float ys[CHUNK * OCH];      // 11.3 KB
    __shared__ float xsf[CHUNK * 80];      // 14.1 KB
    __shared__ int offs[80];

    const int tid = threadIdx.x;
    const int kt = blockIdx.x;
    const int band = blockIdx.y;

    if (kt < 5) {
        if (tid < 80) {
            int k = kt * 80 + tid;
            int ic = k / 25, rem = k - ic * 25;
            int ki = rem / 5, kj = rem - ki * 5;
            offs[tid] = ic * (INS * INS) + ki * INS + kj + band * INS;
        }
        __syncthreads();

        const int ty = tid >> 4;
        const int tx = tid & 15;
        const int oc0 = ty * 8;
        const int kk0 = tx * 5;

        ull acc2[4][5];
#pragma unroll
        for (int r = 0; r < 4; r++)
#pragma unroll
            for (int u = 0; u < 5; u++) acc2[r][u] = 0ULL;

        for (int ch = 0; ch < PIX_PER_BAND / CHUNK; ch++) {
            int pbase = band * PIX_PER_BAND + ch * CHUNK;
            const float4* ysrc = (const float4*)(g_y + pbase * OCH);
            for (int v = tid; v < CHUNK * OCH / 4; v += 128)
                ((float4*)ys)[v] = ysrc[v];
            for (int idx = tid; idx < CHUNK * 80; idx += 128) {
                int p = idx / 80, kk = idx - p * 80;
                xsf[idx] = x[offs[kk] + ch * CHUNK + p];
            }
            __syncthreads();

            for (int p = 0; p < CHUNK; p++) {
                const ulonglong2* yp = (const ulonglong2*)&ys[p * OCH + oc0];
                ulonglong2 ya = yp[0], yb = yp[1];
                ull yr[4] = {ya.x, ya.y, yb.x, yb.y};
                ull xv2[5];
#pragma unroll
                for (int u = 0; u < 5; u++) {
                    float v = xsf[p * 80 + kk0 + u];
                    xv2[u] = pack2(v, v);
                }
#pragma unroll
                for (int u = 0; u < 5; u++)
#pragma unroll
                    for (int r = 0; r < 4; r++)
                        FMA2(acc2[r][u], yr[r], xv2[u]);
            }
            __syncthreads();
        }

        float* Cp = &g_Cpart[band * (OCH * KTOT)];
#pragma unroll
        for (int r = 0; r < 4; r++)
#pragma unroll
            for (int u = 0; u < 5; u++) {
                float2 f = unpack2(acc2[r][u]);
                int col = kt * 80 + kk0 + u;
                Cp[(oc0 + 2 * r) * KTOT + col] = f.x;
                Cp[(oc0 + 2 * r + 1) * KTOT + col] = f.y;
            }
    } else {
        // ---------- y^T @ y + column sums ----------
        const int a = tid >> 1;
        const int bq = (tid & 1) * 32;
        ull acc2[16];
#pragma unroll
        for (int w = 0; w < 16; w++) acc2[w] = 0ULL;
        float csum = 0.f;

        for (int ch = 0; ch < PIX_PER_BAND / CHUNK; ch++) {
            int pbase = band * PIX_PER_BAND + ch * CHUNK;
            const float4* ysrc = (const float4*)(g_y + pbase * OCH);
            for (int v = tid; v < CHUNK * OCH / 4; v += 128)
                ((float4*)ys)[v] = ysrc[v];
            __syncthreads();

            for (int p = 0; p < CHUNK; p++) {
                float ya = ys[p * OCH + a];
                ull ya2 = pack2(ya, ya);
                const ulonglong2* yb = (const ulonglong2*)&ys[p * OCH + bq];
#pragma unroll
                for (int w = 0; w < 8; w++) {
                    ulonglong2 v = yb[w];
                    FMA2(acc2[2 * w],     ya2, v.x);
                    FMA2(acc2[2 * w + 1], ya2, v.y);
                }
                if ((tid & 1) == 0) csum += ya;
            }
            __syncthreads();
        }

        float* Yp = &g_ytypart[band * (OCH * OCH) + a * OCH + bq];
#pragma unroll
        for (int w = 0; w < 16; w++) {
            float2 f = unpack2(acc2[w]);
            Yp[2 * w] = f.x;
            Yp[2 * w + 1] = f.y;
        }
        if ((tid & 1) == 0) g_colpart[band * OCH + a] = csum;
    }
}

// ======================================================================
// K3: reduce stage 1: 220 bands -> 20 groups of 11.
// grid (29, 20), 256 threads.
// ======================================================================
__global__ void k_reduce1()
{
    int e = blockIdx.x * 256 + threadIdx.x;
    int g = blockIdx.y;
    if (e < 6400) {
        const float4* P = (const float4*)g_Cpart;
        float4 s = make_float4(0.f, 0.f, 0.f, 0.f);
#pragma unroll
        for (int b = 0; b < 11; b++) {
            float4 v = P[(g * 11 + b) * 6400 + e];
            s.x += v.x; s.y += v.y; s.z += v.z; s.w += v.w;
        }
        ((float4*)g_Cred)[g * 6400 + e] = s;
    } else if (e < 6400 + 1024) {
        int i = e - 6400;
        const float4* P = (const float4*)g_ytypart;
        float4 s = make_float4(0.f, 0.f, 0.f, 0.f);
#pragma unroll
        for (int b = 0; b < 11; b++) {
            float4 v = P[(g * 11 + b) * 1024 + i];
            s.x += v.x; s.y += v.y; s.z += v.z; s.w += v.w;
        }
        ((float4*)g_ytyred)[g * 1024 + i] = s;
    }
}

// ======================================================================
// K4: reduce stage 2 (+ exp_new / gfp in block 0). grid 29, 256 thr.
// ======================================================================
__global__ void k_reduce2(const float* __restrict__ exp_avg,
                          float* __restrict__ dout)
{
    int e = blockIdx.x * 256 + threadIdx.x;
    if (e < 6400) {
        const float4* P = (const float4*)g_Cred;
        float4 s = make_float4(0.f, 0.f, 0.f, 0.f);
#pragma unroll
        for (int gg = 0; gg < 20; gg++) {
            float4 v = P[gg * 6400 + e];
            s.x += v.x; s.y += v.y; s.z += v.z; s.w += v.w;
        }
        ((float4*)g_Cfin)[e] = s;
    } else if (e < 6400 + 1024) {
        int i = e - 6400;
        const float4* P = (const float4*)g_ytyred;
        float4 s = make_float4(0.f, 0.f, 0.f, 0.f);
#pragma unroll
        for (int gg = 0; gg < 20; gg++) {
            float4 v = P[gg * 1024 + i];
            s.x += v.x; s.y += v.y; s.z += v.z; s.w += v.w;
        }
        ((float4*)g_ytyF)[i] = s;
    }

    if (blockIdx.x == 0) {
        __shared__ float sh[OCH];
        int t = threadIdx.x;
        if (t < OCH) {
            float cs = 0.f;
#pragma unroll 10
            for (int b = 0; b < NBANDS; b++) cs += g_colpart[b * OCH + t];
            float en = 0.99f * exp_avg[t] + (1.0f - 0.99f) * (cs / (float)NB);
            sh[t] = en;
            dout[OUT_OFF_EXP + t] = en;
        }
        __syncthreads();
        if (t < OCH) {
            float s = 0.f;
            for (int i = 0; i < OCH; i++) s += sh[i];
            float A = sh[t] / (s * (1.0f / (float)OCH));
            g_gfp[t] = 0.01f * tanhf(-0.01f * (A - 1.0f)) + 1.0f;
        }
    }
}

// ======================================================================
// K5: weight update.
// ======================================================================
__global__ void k_wupd(const float* __restrict__ W, float* __restrict__ dout)
{
    int idx = blockIdx.x * 256 + threadIdx.x;
    if (idx >= OCH * KTOT) return;
    int oc = idx / KTOT;
    int k = idx - oc * KTOT;
    float dot = 0.f;
#pragma unroll 8
    for (int b = 0; b < OCH; b++)
        dot += g_ytyF[oc * OCH + b] * W[b * KTOT + k];
    const float LRN = (float)(0.005 / 48400.0);
    float d = LRN * (g_Cfin[idx] - dot);
    float wn = fmaxf(W[idx] + d, 0.f);
    dout[OUT_OFF_W + idx] = wn * g_gfp[oc];
}

// ======================================================================
extern "C" void kernel_launch(void* const* d_in, const int* in_sizes, int n_in,
                              void* d_out, int out_size)
{
    const float* x  = (const float*)d_in[0];
    const float* W  = (const float*)d_in[1];
    const float* ea = (const float*)d_in[2];
    float* dout = (float*)d_out;

    k_prep<<<100, 256>>>(W);
    dim3 g1(28, 28);
    k_conv<<<g1, 128>>>(x, dout);
    dim3 g2(6, NBANDS);
    k_hebb<<<g2, 128>>>(x);
    dim3 g3(29, 20);
    k_reduce1<<<g3, 256>>>();
    k_reduce2<<<29, 256>>>(ea, dout);
    k_wupd<<<100, 256>>>(W, dout);
}

// round 5
// speedup vs baseline: 1.5428x; 1.5428x over previous
#include <cuda_runtime.h>
#include <cuda_bf16.h>
#include <cstdint>

typedef unsigned long long ull;

// ---------------- problem constants ----------------
#define INS   224
#define NH    220
#define NB    48400
#define ICH   16
#define OCH   64
#define KTOT  400

#define OUT_OFF_W   (OCH*NB)
#define OUT_OFF_EXP (OUT_OFF_W + OCH*KTOT)

#define MB   110          // ytxf bands (2 image rows each)
#define PPB  440          // pixels per band
#define YTY_BANDS 220

// ---------------- scratch ----------------
__device__ float g_Wt[KTOT * OCH];                    // [ic][25][oc]
__device__ float g_Cpart[MB * 512 * OCH];             // 14.4MB, [band][kk][oc]
__device__ float g_ytypart[YTY_BANDS * OCH * OCH];    // 3.6MB
__device__ float g_colpart[YTY_BANDS * OCH];
__device__ float g_Cfin[512 * OCH];                   // [kk][oc]
__device__ float g_ytyF[OCH * OCH];
__device__ float g_gfp[OCH];

// ---------------- f32x2 helpers ----------------
__device__ __forceinline__ ull pack2(float lo, float hi) {
    ull r; asm("mov.b64 %0, {%1,%2};" : "=l"(r) : "f"(lo), "f"(hi)); return r;
}
__device__ __forceinline__ float2 unpack2(ull v) {
    float2 f; asm("mov.b64 {%0,%1}, %2;" : "=f"(f.x), "=f"(f.y) : "l"(v)); return f;
}
#define FMA2(acc, a, b) asm("fma.rn.f32x2 %0, %1, %2, %0;" : "+l"(acc) : "l"(a), "l"(b))

// ======================================================================
// K0: transpose W -> g_Wt[ic*1600 + kk*64 + oc]
// ======================================================================
__global__ void k_prep(const float* __restrict__ W)
{
    int idx = blockIdx.x * 256 + threadIdx.x;
    if (idx >= KTOT * OCH) return;
    int oc = idx & 63;
    int t  = idx >> 6;
    int ic = t / 25, kk = t - ic * 25;
    g_Wt[idx] = W[oc * KTOT + ic * 25 + kk];
}

// ======================================================================
// K1: conv + inhibition (fp32/FFMA2). grid (14,28), 128 thr.
// Thread: 4 px x 16 oc. Writes dout (NCHW).
// ======================================================================
__global__ void __launch_bounds__(128)
k_conv(const float* __restrict__ x, float* __restrict__ dout)
{
    __shared__ float xs[12 * 21];
    __shared__ float ws[25 * 64];
    __shared__ float mtmp[4][128];

    const int tid = threadIdx.x;
    const int ocg = tid & 3;
    const int pg  = tid >> 2;
    const int li  = pg >> 2;
    const int lj0 = (pg & 3) * 4;
    const int i0  = blockIdx.y * 8;
    const int j0  = blockIdx.x * 16;
    const int oc0 = ocg * 16;

    ull acc2[4][8];
#pragma unroll
    for (int q = 0; q < 4; q++)
#pragma unroll
        for (int w = 0; w < 8; w++) acc2[q][w] = 0ULL;

    const int xbase = li * 21 + lj0;

    for (int ic = 0; ic < ICH; ic++) {
        __syncthreads();
        for (int lin = tid; lin < 12 * 21; lin += 128) {
            int r = lin / 21, c = lin - r * 21;
            int gi = min(i0 + r, INS - 1);
            int gj = min(j0 + c, INS - 1);
            xs[lin] = x[ic * (INS * INS) + gi * INS + gj];
        }
        const float4* wsrc = (const float4*)(g_Wt + ic * 1600);
        for (int v = tid; v < 400; v += 128)
            ((float4*)ws)[v] = wsrc[v];
        __syncthreads();

#pragma unroll 1
        for (int ki = 0; ki < 5; ki++) {
#pragma unroll
            for (int kj = 0; kj < 5; kj++) {
                ull xv2[4];
#pragma unroll
                for (int q = 0; q < 4; q++) {
                    float v = xs[xbase + ki * 21 + kj + q];
                    xv2[q] = pack2(v, v);
                }
                const ulonglong2* wp =
                    (const ulonglong2*)&ws[(ki * 5 + kj) * 64 + oc0];
#pragma unroll
                for (int w = 0; w < 4; w++) {
                    ulonglong2 ww = wp[w];
#pragma unroll
                    for (int q = 0; q < 4; q++) {
                        FMA2(acc2[q][2 * w],     xv2[q], ww.x);
                        FMA2(acc2[q][2 * w + 1], xv2[q], ww.y);
                    }
                }
            }
        }
    }

#pragma unroll
    for (int q = 0; q < 4; q++) {
        float m = 0.f;
#pragma unroll
        for (int w = 0; w < 8; w++) {
            float2 f = unpack2(acc2[q][w]);
            m = fmaxf(m, fmaxf(f.x, f.y));
        }
        mtmp[ocg][pg * 4 + q] = m;
    }
    __syncthreads();

    const int i = i0 + li;
    const int j = j0 + lj0;
    float minv[4];
#pragma unroll
    for (int q = 0; q < 4; q++) {
        float m = fmaxf(fmaxf(mtmp[0][pg * 4 + q], mtmp[1][pg * 4 + q]),
                        fmaxf(mtmp[2][pg * 4 + q], mtmp[3][pg * 4 + q]));
        minv[q] = 1.f / (m + 1e-9f);
    }

    if (i < NH && j < NH) {
        const int p = i * NH + j;
#pragma unroll
        for (int w = 0; w < 8; w += 2) {
            float vals[4][4];
#pragma unroll
            for (int q = 0; q < 4; q++) {
                float2 fa = unpack2(acc2[q][w]);
                float2 fb = unpack2(acc2[q][w + 1]);
                vals[q][0] = fa.x; vals[q][1] = fa.y;
                vals[q][2] = fb.x; vals[q][3] = fb.y;
            }
#pragma unroll
            for (int q = 0; q < 4; q++)
#pragma unroll
                for (int o = 0; o < 4; o++) {
                    float v = fmaxf(vals[q][o], 0.f) * minv[q];
                    float v2 = v * v;
                    vals[q][o] = v2 * v2 * v;
                }
            int obase = oc0 + 2 * w;
#pragma unroll
            for (int o = 0; o < 4; o++)
                *(float4*)&dout[(obase + o) * NB + p] =
                    make_float4(vals[0][o], vals[1][o], vals[2][o], vals[3][o]);
        }
    }
}

// ======================================================================
// K2: y^T @ y + colsums (fp32). grid 220, 128 thr.
// ======================================================================
__global__ void __launch_bounds__(128)
k_yty(const float* __restrict__ dout)
{
    __shared__ float ys[64 * 81];
    const int tid = threadIdx.x;
    const int band = blockIdx.x;
    const int ty = tid >> 3, tx = tid & 7;
    const int a0 = ty * 4, b0 = tx * 8;

    float acc[4][8];
#pragma unroll
    for (int i = 0; i < 4; i++)
#pragma unroll
        for (int j = 0; j < 8; j++) acc[i][j] = 0.f;
    float csA[4] = {0.f, 0.f, 0.f, 0.f};

    for (int ch = 0; ch < 5; ch++) {
        __syncthreads();
        int p0 = band * NH + ch * 44;
        for (int idx = tid; idx < 64 * 11; idx += 128) {
            int row = idx / 11, c4 = idx - row * 11;
            float4 v = *(const float4*)(dout + (size_t)row * NB + p0 + c4 * 4);
            float* d = &ys[row * 81 + c4 * 4];
            d[0] = v.x; d[1] = v.y; d[2] = v.z; d[3] = v.w;
        }
        __syncthreads();

        for (int p = 0; p < 44; p++) {
            float av[4], bv[8];
#pragma unroll
            for (int i = 0; i < 4; i++) av[i] = ys[(a0 + i) * 81 + p];
#pragma unroll
            for (int j = 0; j < 8; j++) bv[j] = ys[(b0 + j) * 81 + p];
#pragma unroll
            for (int i = 0; i < 4; i++)
#pragma unroll
                for (int j = 0; j < 8; j++) acc[i][j] += av[i] * bv[j];
            if (tx == 0) {
#pragma unroll
                for (int i = 0; i < 4; i++) csA[i] += av[i];
            }
        }
    }

    float* Yp = &g_ytypart[(size_t)band * 4096];
#pragma unroll
    for (int i = 0; i < 4; i++) {
        *(float4*)&Yp[(a0 + i) * 64 + b0] =
            make_float4(acc[i][0], acc[i][1], acc[i][2], acc[i][3]);
        *(float4*)&Yp[(a0 + i) * 64 + b0 + 4] =
            make_float4(acc[i][4], acc[i][5], acc[i][6], acc[i][7]);
    }
    if (tx == 0)
#pragma unroll
        for (int i = 0; i < 4; i++)
            g_colpart[band * OCH + a0 + i] = csA[i];
}

// ======================================================================
// K3: y^T @ xf via mma.sync bf16 (HMMA). grid (110 bands, 4 kt), 256 thr.
// Block: D[128 kk x 64 oc] over 440 px, chunks of 64 px.
// Warp w: kk rows [w*16, w*16+16), all 64 oc.
// smem pitch 72 bf16 (36 u32) -> conflict-free fragment loads.
// ======================================================================
#define APITCH 36   // u32 per A/B row (72 bf16)

__global__ void __launch_bounds__(256)
k_ytxf_mma(const float* __restrict__ x, const float* __restrict__ dout)
{
    __shared__ uint32_t As[128 * APITCH];   // 18.4KB
    __shared__ uint32_t Bs[64 * APITCH];    // 9.2KB
    __shared__ int offs[128];
    __shared__ int bases[PPB];

    const int tid  = threadIdx.x;
    const int band = blockIdx.x;
    const int kt   = blockIdx.y;
    const int w    = tid >> 5;
    const int lane = tid & 31;
    const int g    = lane >> 2;    // groupID
    const int t    = lane & 3;     // thread-in-group

    // per-kt A-row gather offsets
    if (tid < 128) {
        int kkg = kt * 128 + tid;
        if (kkg < KTOT) {
            int ic = kkg / 25, rem = kkg - ic * 25;
            int ki = rem / 5, kj = rem - ki * 5;
            offs[tid] = ic * (INS * INS) + ki * INS + kj;
        } else offs[tid] = -1;
    }
    // pixel base addresses for this band (2 image rows)
    for (int p = tid; p < PPB; p += 256) {
        int i = band * 2 + (p >= NH ? 1 : 0);
        int j = (p >= NH) ? p - NH : p;
        bases[p] = i * INS + j;
    }

    float c[8][4];
#pragma unroll
    for (int n = 0; n < 8; n++)
#pragma unroll
        for (int q = 0; q < 4; q++) c[n][q] = 0.f;

    for (int ch = 0; ch < 7; ch++) {        // 7 chunks of 64 px (last padded)
        __syncthreads();
        const int px0 = ch * 64;
        // ---- fill A: 128 rows x 32 u32 ----
        for (int idx = tid; idx < 128 * 32; idx += 256) {
            int row = idx >> 5, pc = idx & 31;
            int px = px0 + 2 * pc;
            int o = offs[row];
            float v0 = 0.f, v1 = 0.f;
            if (o >= 0 && px < PPB) {
                v0 = x[o + bases[px]];
                v1 = x[o + bases[px + 1]];
            }
            __nv_bfloat162 h = __float22bfloat162_rn(make_float2(v0, v1));
            As[row * APITCH + pc] = *(uint32_t*)&h;
        }
        // ---- fill B: 64 rows x 32 u32 ----
        for (int idx = tid; idx < 64 * 32; idx += 256) {
            int row = idx >> 5, pc = idx & 31;
            int px = px0 + 2 * pc;
            float v0 = 0.f, v1 = 0.f;
            if (px < PPB) {
                const float* src = dout + (size_t)row * NB + band * PPB + px;
                v0 = src[0]; v1 = src[1];
            }
            __nv_bfloat162 h = __float22bfloat162_rn(make_float2(v0, v1));
            Bs[row * APITCH + pc] = *(uint32_t*)&h;
        }
        __syncthreads();

        // ---- 4 k16 steps x 8 n-tiles ----
#pragma unroll
        for (int ks = 0; ks < 4; ks++) {
            const uint32_t* Ar = &As[(w * 16 + g) * APITCH + ks * 8 + t];
            uint32_t a0 = Ar[0];
            uint32_t a2 = Ar[4];
            uint32_t a1 = Ar[8 * APITCH];
            uint32_t a3 = Ar[8 * APITCH + 4];
#pragma unroll
            for (int nt = 0; nt < 8; nt++) {
                const uint32_t* Br = &Bs[(nt * 8 + g) * APITCH + ks * 8 + t];
                uint32_t b0 = Br[0];
                uint32_t b1 = Br[4];
                asm volatile(
                    "mma.sync.aligned.m16n8k16.row.col.f32.bf16.bf16.f32 "
                    "{%0,%1,%2,%3},{%4,%5,%6,%7},{%8,%9},{%0,%1,%2,%3};"
                    : "+f"(c[nt][0]), "+f"(c[nt][1]), "+f"(c[nt][2]), "+f"(c[nt][3])
                    : "r"(a0), "r"(a1), "r"(a2), "r"(a3), "r"(b0), "r"(b1));
            }
        }
    }

    // ---- epilogue: D rows w*16+g / +8, cols nt*8 + 2t ----
    float* dst = g_Cpart + ((size_t)band * 512 + kt * 128 + w * 16) * 64;
#pragma unroll
    for (int nt = 0; nt < 8; nt++) {
        *(float2*)&dst[(g)     * 64 + nt * 8 + 2 * t] = make_float2(c[nt][0], c[nt][1]);
        *(float2*)&dst[(g + 8) * 64 + nt * 8 + 2 * t] = make_float2(c[nt][2], c[nt][3]);
    }
}

// ======================================================================
// K4: reduce partials + exp_new/gfp. grid 37 x 256.
// ======================================================================
__global__ void k_reduce(const float* __restrict__ exp_avg,
                         float* __restrict__ dout)
{
    int e = blockIdx.x * 256 + threadIdx.x;
    if (e < 8192) {
        const float4* P = (const float4*)g_Cpart;
        float4 s = make_float4(0.f, 0.f, 0.f, 0.f);
        for (int b = 0; b < MB; b++) {
            float4 v = P[(size_t)b * 8192 + e];
            s.x += v.x; s.y += v.y; s.z += v.z; s.w += v.w;
        }
        ((float4*)g_Cfin)[e] = s;
    } else if (e < 9216) {
        int i = e - 8192;
        const float4* P = (const float4*)g_ytypart;
        float4 s = make_float4(0.f, 0.f, 0.f, 0.f);
        for (int b = 0; b < YTY_BANDS; b++) {
            float4 v = P[(size_t)b * 1024 + i];
            s.x += v.x; s.y += v.y; s.z += v.z; s.w += v.w;
        }
        ((float4*)g_ytyF)[i] = s;
    }

    if (blockIdx.x == 36) {
        __shared__ float sh[OCH];
        int t = threadIdx.x;
        if (t < OCH) {
            float cs = 0.f;
#pragma unroll 10
            for (int b = 0; b < YTY_BANDS; b++) cs += g_colpart[b * OCH + t];
            float en = 0.99f * exp_avg[t] + (1.0f - 0.99f) * (cs / (float)NB);
            sh[t] = en;
            dout[OUT_OFF_EXP + t] = en;
        }
        __syncthreads();
        if (t < OCH) {
            float s = 0.f;
            for (int i = 0; i < OCH; i++) s += sh[i];
            float A = sh[t] / (s * (1.0f / (float)OCH));
            g_gfp[t] = 0.01f * tanhf(-0.01f * (A - 1.0f)) + 1.0f;
        }
    }
}

// ======================================================================
// K5: weight update. C stored [kk][oc].
// ======================================================================
__global__ void k_wupd(const float* __restrict__ W, float* __restrict__ dout)
{
    int idx = blockIdx.x * 256 + threadIdx.x;
    if (idx >= OCH * KTOT) return;
    int oc = idx / KTOT;
    int k = idx - oc * KTOT;
    float dot = 0.f;
#pragma unroll 8
    for (int b = 0; b < OCH; b++)
        dot += g_ytyF[oc * OCH + b] * W[b * KTOT + k];
    const float LRN = (float)(0.005 / 48400.0);
    float d = LRN * (g_Cfin[k * 64 + oc] - dot);
    float wn = fmaxf(W[idx] + d, 0.f);
    dout[OUT_OFF_W + idx] = wn * g_gfp[oc];
}

// ======================================================================
extern "C" void kernel_launch(void* const* d_in, const int* in_sizes, int n_in,
                              void* d_out, int out_size)
{
    const float* x  = (const float*)d_in[0];
    const float* W  = (const float*)d_in[1];
    const float* ea = (const float*)d_in[2];
    float* dout = (float*)d_out;

    k_prep<<<100, 256>>>(W);
    dim3 g1(14, 28);
    k_conv<<<g1, 128>>>(x, dout);
    k_yty<<<YTY_BANDS, 128>>>(dout);
    dim3 g3(MB, 4);
    k_ytxf_mma<<<g3, 256>>>(x, dout);
    k_reduce<<<37, 256>>>(ea, dout);
    k_wupd<<<100, 256>>>(W, dout);
}

// round 6
// speedup vs baseline: 2.3389x; 1.5160x over previous
#include <cuda_runtime.h>
#include <cuda_bf16.h>
#include <cstdint>

// ---------------- problem constants ----------------
#define INS   224
#define NH    220
#define NB    48400
#define ICH   16
#define OCH   64
#define KTOT  400
#define XSZ   (ICH*INS*INS)      // 802816

#define OUT_OFF_W   (OCH*NB)
#define OUT_OFF_EXP (OUT_OFF_W + OCH*KTOT)

#define MB    110                // ytxf bands (2 image rows)
#define PPB   440
#define YP    48640              // g_yh row pitch (>= 217*224, mult of 128)
#define YTYB  217                // yty blocks of 224 px

// ---------------- scratch ----------------
__device__ __nv_bfloat16 g_xh[XSZ];
__device__ __nv_bfloat16 g_xl[XSZ];
__device__ __nv_bfloat16 g_xhs[XSZ];         // g_xhs[e] = bf16(x[e+1])
__device__ __nv_bfloat16 g_Wh[OCH * KTOT];
__device__ __nv_bfloat16 g_Wl[OCH * KTOT];
__device__ __nv_bfloat16 g_yh[OCH * YP];     // bf16 y, [oc][px], pad zeroed
__device__ float g_Cpart[MB * 512 * OCH];
__device__ float g_ytypart[YTYB * OCH * OCH];
__device__ float g_colF[OCH];
__device__ float g_Cfin[512 * OCH];
__device__ float g_ytyF[OCH * OCH];
__device__ float g_gfp[OCH];

#define MMA16816(c, a0,a1,a2,a3, b0,b1) \
  asm volatile("mma.sync.aligned.m16n8k16.row.col.f32.bf16.bf16.f32 " \
    "{%0,%1,%2,%3},{%4,%5,%6,%7},{%8,%9},{%0,%1,%2,%3};" \
    : "+f"((c)[0]),"+f"((c)[1]),"+f"((c)[2]),"+f"((c)[3]) \
    : "r"(a0),"r"(a1),"r"(a2),"r"(a3),"r"(b0),"r"(b1))

// ======================================================================
// K0a: x -> bf16 hi/lo + shifted hi copy
// ======================================================================
__global__ void k_cvt_x(const float* __restrict__ x)
{
    int idx = blockIdx.x * 256 + threadIdx.x;
    if (idx >= XSZ) return;
    float v = x[idx];
    __nv_bfloat16 h = __float2bfloat16(v);
    g_xh[idx] = h;
    g_xl[idx] = __float2bfloat16(v - __bfloat162float(h));
    g_xhs[idx] = (idx + 1 < XSZ) ? __float2bfloat16(x[idx + 1])
                                 : __float2bfloat16(0.f);
}

// ======================================================================
// K0b: W -> bf16 hi/lo ; zero g_yh pad region
// ======================================================================
__global__ void k_cvt_w(const float* __restrict__ W)
{
    int idx = blockIdx.x * 256 + threadIdx.x;
    if (idx < OCH * KTOT) {
        float v = W[idx];
        __nv_bfloat16 h = __float2bfloat16(v);
        g_Wh[idx] = h;
        g_Wl[idx] = __float2bfloat16(v - __bfloat162float(h));
    } else if (idx < OCH * KTOT + OCH * (YP - NB)) {
        int p = idx - OCH * KTOT;
        int oc = p / (YP - NB), off = p - oc * (YP - NB);
        g_yh[oc * YP + NB + off] = __float2bfloat16(0.f);
    }
}

// ======================================================================
// K1: conv + inhibition via split-bf16 MMA.
// grid (2 halves, 220 rows), 224 thr (7 warps). Warp = 16 px x 64 oc.
// ======================================================================
__global__ void __launch_bounds__(224)
k_conv_mma(float* __restrict__ dout)
{
    __shared__ unsigned short xsh[80 * 120];
    __shared__ unsigned short xsl[80 * 120];
    __shared__ uint32_t wsh[64 * 17];
    __shared__ uint32_t wsl[64 * 17];

    const int tid = threadIdx.x;
    const int w = tid >> 5, lane = tid & 31;
    const int g = lane >> 2, t = lane & 3;
    const int h = blockIdx.x;           // 0/1
    const int i = blockIdx.y;           // image row 0..219
    const int J0 = h * 108;

    // ---- stage x rows: 80 (ic,ki) rows x 116 bf16 (58 u32) ----
    {
        const uint32_t* xh2 = (const uint32_t*)g_xh;
        const uint32_t* xl2 = (const uint32_t*)g_xl;
        uint32_t* dsth = (uint32_t*)xsh;
        uint32_t* dstl = (uint32_t*)xsl;
        for (int idx = tid; idx < 80 * 58; idx += 224) {
            int r = idx / 58, u = idx - r * 58;
            int ic = r / 5, ki = r - ic * 5;
            int e2 = ic * 25088 + (i + ki) * 112 + h * 54 + u;
            dsth[r * 60 + u] = xh2[e2];
            dstl[r * 60 + u] = xl2[e2];
        }
    }

    float c[8][4];
#pragma unroll
    for (int nt = 0; nt < 8; nt++)
#pragma unroll
        for (int q = 0; q < 4; q++) c[nt][q] = 0.f;

    const int pxA = (w << 4) + g;
    const int pxB = pxA + 8;
    const uint32_t* wh2g = (const uint32_t*)g_Wh;
    const uint32_t* wl2g = (const uint32_t*)g_Wl;

    for (int s = 0; s < 13; s++) {
        __syncthreads();
        // ---- stage W chunk: 64 oc x nk k ----
        const int k0s = s * 32;
        const int nk = (s < 12) ? 32 : 16;
        const int nu = nk >> 1;
        for (int idx = tid; idx < 64 * nu; idx += 224) {
            int row = idx / nu, u = idx - row * nu;
            int e2 = (row * 400 + k0s) >> 1;
            wsh[row * 17 + u] = wh2g[e2 + u];
            wsl[row * 17 + u] = wl2g[e2 + u];
        }
        __syncthreads();

        const int nks = (s < 12) ? 2 : 1;
        for (int ksl = 0; ksl < nks; ksl++) {
            const int k0 = k0s + ksl * 16;
            // ---- A fragments (hi & lo) gathered from row cache ----
            const int kb0 = k0 + 2 * t;
            const int kb1 = kb0 + 8;
            int r0 = kb0 / 5, kj0 = kb0 - r0 * 5;
            int r0b = (kj0 == 4) ? r0 + 1 : r0;
            int kj0b = (kj0 == 4) ? 0 : kj0 + 1;
            int r1 = kb1 / 5, kj1 = kb1 - r1 * 5;
            int r1b = (kj1 == 4) ? r1 + 1 : r1;
            int kj1b = (kj1 == 4) ? 0 : kj1 + 1;

            const int a00 = r0 * 120 + kj0, a01 = r0b * 120 + kj0b;
            const int a10 = r1 * 120 + kj1, a11 = r1b * 120 + kj1b;

            uint32_t ah0 = (uint32_t)xsh[a00 + pxA] | ((uint32_t)xsh[a01 + pxA] << 16);
            uint32_t ah1 = (uint32_t)xsh[a00 + pxB] | ((uint32_t)xsh[a01 + pxB] << 16);
            uint32_t ah2 = (uint32_t)xsh[a10 + pxA] | ((uint32_t)xsh[a11 + pxA] << 16);
            uint32_t ah3 = (uint32_t)xsh[a10 + pxB] | ((uint32_t)xsh[a11 + pxB] << 16);
            uint32_t al0 = (uint32_t)xsl[a00 + pxA] | ((uint32_t)xsl[a01 + pxA] << 16);
            uint32_t al1 = (uint32_t)xsl[a00 + pxB] | ((uint32_t)xsl[a01 + pxB] << 16);
            uint32_t al2 = (uint32_t)xsl[a10 + pxA] | ((uint32_t)xsl[a11 + pxA] << 16);
            uint32_t al3 = (uint32_t)xsl[a10 + pxB] | ((uint32_t)xsl[a11 + pxB] << 16);

#pragma unroll
            for (int nt = 0; nt < 8; nt++) {
                const int brow = (nt * 8 + g) * 17 + ksl * 8 + t;
                uint32_t bh0 = wsh[brow], bh1 = wsh[brow + 4];
                uint32_t bl0 = wsl[brow], bl1 = wsl[brow + 4];
                MMA16816(c[nt], ah0, ah1, ah2, ah3, bh0, bh1);
                MMA16816(c[nt], al0, al1, al2, al3, bh0, bh1);
                MMA16816(c[nt], ah0, ah1, ah2, ah3, bl0, bl1);
            }
        }
    }

    // ---- inhibition + writeback ----
    float m0 = 0.f, m1 = 0.f;
#pragma unroll
    for (int nt = 0; nt < 8; nt++) {
        m0 = fmaxf(m0, fmaxf(c[nt][0], c[nt][1]));
        m1 = fmaxf(m1, fmaxf(c[nt][2], c[nt][3]));
    }
    m0 = fmaxf(m0, __shfl_xor_sync(0xFFFFFFFFu, m0, 1));
    m0 = fmaxf(m0, __shfl_xor_sync(0xFFFFFFFFu, m0, 2));
    m1 = fmaxf(m1, __shfl_xor_sync(0xFFFFFFFFu, m1, 1));
    m1 = fmaxf(m1, __shfl_xor_sync(0xFFFFFFFFu, m1, 2));
    const float inv0 = 1.f / (m0 + 1e-9f);
    const float inv1 = 1.f / (m1 + 1e-9f);

    const int pxg = i * NH + J0 + (w << 4) + g;
#pragma unroll
    for (int nt = 0; nt < 8; nt++) {
        const int oc = nt * 8 + 2 * t;
        float v;
        v = fmaxf(c[nt][0], 0.f) * inv0; v = (v * v) * (v * v) * v;
        dout[(size_t)oc * NB + pxg] = v;
        g_yh[(size_t)oc * YP + pxg] = __float2bfloat16(v);
        v = fmaxf(c[nt][1], 0.f) * inv0; v = (v * v) * (v * v) * v;
        dout[(size_t)(oc + 1) * NB + pxg] = v;
        g_yh[(size_t)(oc + 1) * YP + pxg] = __float2bfloat16(v);
        v = fmaxf(c[nt][2], 0.f) * inv1; v = (v * v) * (v * v) * v;
        dout[(size_t)oc * NB + pxg + 8] = v;
        g_yh[(size_t)oc * YP + pxg + 8] = __float2bfloat16(v);
        v = fmaxf(c[nt][3], 0.f) * inv1; v = (v * v) * (v * v) * v;
        dout[(size_t)(oc + 1) * NB + pxg + 8] = v;
        g_yh[(size_t)(oc + 1) * YP + pxg + 8] = __float2bfloat16(v);
    }
}

// ======================================================================
// K2: y^T @ xf via MMA (bf16 preconverted). grid (110, 4), 256 thr.
// ======================================================================
#define APITCH 36

__global__ void __launch_bounds__(256)
k_ytxf_mma()
{
    __shared__ uint32_t As[128 * APITCH];
    __shared__ uint32_t Bs[64 * APITCH];
    __shared__ int offs[128];
    __shared__ int bases[PPB];

    const int tid  = threadIdx.x;
    const int band = blockIdx.x;
    const int kt   = blockIdx.y;
    const int w    = tid >> 5;
    const int lane = tid & 31;
    const int g    = lane >> 2;
    const int t    = lane & 3;

    if (tid < 128) {
        int kkg = kt * 128 + tid;
        if (kkg < KTOT) {
            int ic = kkg / 25, rem = kkg - ic * 25;
            int ki = rem / 5, kj = rem - ki * 5;
            offs[tid] = ic * (INS * INS) + ki * INS + kj;
        } else offs[tid] = -1;
    }
    for (int p = tid; p < PPB; p += 256) {
        int ii = band * 2 + (p >= NH ? 1 : 0);
        int jj = (p >= NH) ? p - NH : p;
        bases[p] = ii * INS + jj;
    }

    const uint32_t* xh32  = (const uint32_t*)g_xh;
    const uint32_t* xhs32 = (const uint32_t*)g_xhs;
    const uint32_t* yh32  = (const uint32_t*)g_yh;
    const int bandY = band * PPB;

    float c[8][4];
#pragma unroll
    for (int n = 0; n < 8; n++)
#pragma unroll
        for (int q = 0; q < 4; q++) c[n][q] = 0.f;

    for (int ch = 0; ch < 7; ch++) {
        __syncthreads();
        const int px0 = ch * 64;
        // A: 128 kk rows x 32 u32 (64 px)
        for (int idx = tid; idx < 128 * 32; idx += 256) {
            int row = idx >> 5, pc = idx & 31;
            int px = px0 + 2 * pc;
            uint32_t v = 0;
            int o = offs[row];
            if (o >= 0 && px < PPB) {
                int e = o + bases[px];
                v = (e & 1) ? xhs32[e >> 1] : xh32[e >> 1];
            }
            As[row * APITCH + pc] = v;
        }
        // B: 64 oc rows x 32 u32
        for (int idx = tid; idx < 64 * 32; idx += 256) {
            int row = idx >> 5, pc = idx & 31;
            int px = px0 + 2 * pc;
            uint32_t v = 0;
            if (px < PPB) v = yh32[((size_t)row * YP + bandY + px) >> 1];
            Bs[row * APITCH + pc] = v;
        }
        __syncthreads();

#pragma unroll
        for (int ks = 0; ks < 4; ks++) {
            const uint32_t* Ar = &As[(w * 16 + g) * APITCH + ks * 8 + t];
            uint32_t a0 = Ar[0];
            uint32_t a2 = Ar[4];
            uint32_t a1 = Ar[8 * APITCH];
            uint32_t a3 = Ar[8 * APITCH + 4];
#pragma unroll
            for (int nt = 0; nt < 8; nt++) {
                const uint32_t* Br = &Bs[(nt * 8 + g) * APITCH + ks * 8 + t];
                MMA16816(c[nt], a0, a1, a2, a3, Br[0], Br[4]);
            }
        }
    }

    float* dst = g_Cpart + ((size_t)band * 512 + kt * 128 + w * 16) * 64;
#pragma unroll
    for (int nt = 0; nt < 8; nt++) {
        *(float2*)&dst[(g)     * 64 + nt * 8 + 2 * t] = make_float2(c[nt][0], c[nt][1]);
        *(float2*)&dst[(g + 8) * 64 + nt * 8 + 2 * t] = make_float2(c[nt][2], c[nt][3]);
    }
}

// ======================================================================
// K3: y^T @ y via MMA from g_yh. grid 217, 256 thr.
// ======================================================================
__global__ void __launch_bounds__(256)
k_yty_mma()
{
    const int tid = threadIdx.x;
    const int b = blockIdx.x;
    const int px0 = b * 224;
    const int w = tid >> 5, lane = tid & 31;
    const int g = lane >> 2, t = lane & 3;
    const int m0 = (w & 3) * 16;
    const int ntb = (w >> 2) * 4;

    const uint32_t* yh32 = (const uint32_t*)g_yh;

    float c[4][4];
#pragma unroll
    for (int n = 0; n < 4; n++)
#pragma unroll
        for (int q = 0; q < 4; q++) c[n][q] = 0.f;

#pragma unroll 2
    for (int ks = 0; ks < 14; ks++) {
        const int kb = px0 + ks * 16 + 2 * t;
        uint32_t a0 = yh32[((size_t)(m0 + g) * YP + kb) >> 1];
        uint32_t a1 = yh32[((size_t)(m0 + g + 8) * YP + kb) >> 1];
        uint32_t a2 = yh32[((size_t)(m0 + g) * YP + kb + 8) >> 1];
        uint32_t a3 = yh32[((size_t)(m0 + g + 8) * YP + kb + 8) >> 1];
#pragma unroll
        for (int nt = 0; nt < 4; nt++) {
            const int n = (ntb + nt) * 8 + g;
            uint32_t b0 = yh32[((size_t)n * YP + kb) >> 1];
            uint32_t b1 = yh32[((size_t)n * YP + kb + 8) >> 1];
            MMA16816(c[nt], a0, a1, a2, a3, b0, b1);
        }
    }

    float* dst = g_ytypart + (size_t)b * 4096;
#pragma unroll
    for (int nt = 0; nt < 4; nt++) {
        const int col = (ntb + nt) * 8 + 2 * t;
        *(float2*)&dst[(m0 + g) * 64 + col]     = make_float2(c[nt][0], c[nt][1]);
        *(float2*)&dst[(m0 + g + 8) * 64 + col] = make_float2(c[nt][2], c[nt][3]);
    }
}

// ======================================================================
// K4: column sums of y (fp32, deterministic). grid 64, 256 thr.
// ======================================================================
__global__ void k_colsum(const float* __restrict__ dout)
{
    __shared__ float sh[256];
    const int oc = blockIdx.x, tid = threadIdx.x;
    float s = 0.f;
    for (int px = tid; px < NB; px += 256)
        s += dout[(size_t)oc * NB + px];
    sh[tid] = s;
    __syncthreads();
    for (int st = 128; st > 0; st >>= 1) {
        if (tid < st) sh[tid] += sh[tid + st];
        __syncthreads();
    }
    if (tid == 0) g_colF[oc] = sh[0];
}

// ======================================================================
// K5: reduce partials + exp_new/gfp. grid 37 x 256.
// ======================================================================
__global__ void k_reduce(const float* __restrict__ exp_avg,
                         float* __restrict__ dout)
{
    int e = blockIdx.x * 256 + threadIdx.x;
    if (e < 8192) {
        const float4* P = (const float4*)g_Cpart;
        float4 s = make_float4(0.f, 0.f, 0.f, 0.f);
        for (int b = 0; b < MB; b++) {
            float4 v = P[(size_t)b * 8192 + e];
            s.x += v.x; s.y += v.y; s.z += v.z; s.w += v.w;
        }
        ((float4*)g_Cfin)[e] = s;
    } else if (e < 9216) {
        int i = e - 8192;
        const float4* P = (const float4*)g_ytypart;
        float4 s = make_float4(0.f, 0.f, 0.f, 0.f);
        for (int b = 0; b < YTYB; b++) {
            float4 v = P[(size_t)b * 1024 + i];
            s.x += v.x; s.y += v.y; s.z += v.z; s.w += v.w;
        }
        ((float4*)g_ytyF)[i] = s;
    }

    if (blockIdx.x == 36) {
        __shared__ float sh[OCH];
        int t = threadIdx.x;
        if (t < OCH) {
            float en = 0.99f * exp_avg[t] +
                       (1.0f - 0.99f) * (g_colF[t] / (float)NB);
            sh[t] = en;
            dout[OUT_OFF_EXP + t] = en;
        }
        __syncthreads();
        if (t < OCH) {
            float s = 0.f;
            for (int i = 0; i < OCH; i++) s += sh[i];
            float A = sh[t] / (s * (1.0f / (float)OCH));
            g_gfp[t] = 0.01f * tanhf(-0.01f * (A - 1.0f)) + 1.0f;
        }
    }
}

// ======================================================================
// K6: weight update.
// ======================================================================
__global__ void k_wupd(const float* __restrict__ W, float* __restrict__ dout)
{
    int idx = blockIdx.x * 256 + threadIdx.x;
    if (idx >= OCH * KTOT) return;
    int oc = idx / KTOT;
    int k = idx - oc * KTOT;
    float dot = 0.f;
#pragma unroll 8
    for (int b = 0; b < OCH; b++)
        dot += g_ytyF[oc * OCH + b] * W[b * KTOT + k];
    const float LRN = (float)(0.005 / 48400.0);
    float d = LRN * (g_Cfin[k * 64 + oc] - dot);
    float wn = fmaxf(W[idx] + d, 0.f);
    dout[OUT_OFF_W + idx] = wn * g_gfp[oc];
}

// ======================================================================
extern "C" void kernel_launch(void* const* d_in, const int* in_sizes, int n_in,
                              void* d_out, int out_size)
{
    const float* x  = (const float*)d_in[0];
    const float* W  = (const float*)d_in[1];
    const float* ea = (const float*)d_in[2];
    float* dout = (float*)d_out;

    k_cvt_x<<<(XSZ + 255) / 256, 256>>>(x);
    k_cvt_w<<<(OCH * KTOT + OCH * (YP - NB) + 255) / 256, 256>>>(W);
    dim3 g1(2, 220);
    k_conv_mma<<<g1, 224>>>(dout);
    dim3 g2(MB, 4);
    k_ytxf_mma<<<g2, 256>>>();
    k_yty_mma<<<YTYB, 256>>>();
    k_colsum<<<OCH, 256>>>(dout);
    k_reduce<<<37, 256>>>(ea, dout);
    k_wupd<<<100, 256>>>(W, dout);
}